// round 5
// baseline (speedup 1.0000x reference)
#include <cuda_runtime.h>
#include <cuda_fp16.h>

// SemiConv2d (tropical conv): out[n,oc,h,w] = max_{ic,kh,kw} min(xpad, K)
// x: (8,32,96,96) f32, K: (32,32,3,3) f32, out f32, pad=1 with -inf.
// fp16 HMNMX2, oc-paired accumulators, same-register splats (fold into
// operand modifiers), vectorized LDS (x: 128+32 per row, k: 9 taps/ic in
// 2xLDS.128+LDS.32 reused across kh), ic unroll 2 for load prefetch.

#define N_      8
#define IC_     32
#define OC_     32
#define H_      96
#define W_      96
#define TILE_H  2
#define XROWS   4            // TILE_H + 2 halo rows
#define XS_STRIDE 104        // halves per row: 16B-multiple (208 B); col0,97..103 = -inf
#define K_STRIDE  12         // half2 per (pair, ic): 9 taps + pad -> 48 B, 16B aligned
#define OC_PER_BLK 16
#define THREADS 192

__global__ __launch_bounds__(THREADS)
void semiconv2d_h2v(const float* __restrict__ x,
                    const float* __restrict__ kern,
                    float* __restrict__ out) {
    extern __shared__ __align__(16) char smraw[];
    __half*  xs = (__half*)smraw;                                  // [IC][XROWS][XS_STRIDE]
    __half2* ks = (__half2*)(smraw + (size_t)IC_ * XROWS * XS_STRIDE * sizeof(__half)); // [8][IC][K_STRIDE]

    const int tid    = threadIdx.x;
    const int n      = blockIdx.z;
    const int ocbase = blockIdx.y * OC_PER_BLK;
    const int h0     = blockIdx.x * TILE_H;
    const __half  NEGH = __ushort_as_half((unsigned short)0xFC00);  // -inf
    const __half2 NEG2 = __half2half2(NEGH);

    // ---- load x tile (f32 gmem -> f16 smem, -inf borders & pad cols) ----
    const float* xn = x + (size_t)n * IC_ * H_ * W_;
    for (int e = tid; e < IC_ * XROWS * XS_STRIDE; e += THREADS) {
        int ic  = e / (XROWS * XS_STRIDE);
        int rem = e % (XROWS * XS_STRIDE);
        int r   = rem / XS_STRIDE;
        int c   = rem % XS_STRIDE;
        int g   = h0 - 1 + r;
        __half v = NEGH;
        if (c >= 1 && c <= W_ && g >= 0 && g < H_)
            v = __float2half_rn(xn[(ic * H_ + g) * W_ + (c - 1)]);
        xs[e] = v;
    }
    // ---- kernel slice, paired over adjacent ocs: ks[p][ic][t] = (k[2p], k[2p+1]) ----
    for (int e = tid; e < 8 * IC_ * 9; e += THREADS) {
        int p   = e / (IC_ * 9);
        int rem = e % (IC_ * 9);            // ic*9 + t
        int ic  = rem / 9;
        int t   = rem % 9;
        float a = kern[(ocbase + 2 * p)     * IC_ * 9 + rem];
        float b = kern[(ocbase + 2 * p + 1) * IC_ * 9 + rem];
        ks[(p * IC_ + ic) * K_STRIDE + t] = __floats2half2_rn(a, b);
    }
    __syncthreads();

    // thread -> (h row within tile, 8-wide w strip, one oc pair)
    const int s    = tid % 24;          // 2 h x 12 w-strips
    const int pair = tid / 24;          // 0..7
    const int hl   = s / 12;            // 0..1
    const int w0   = (s % 12) * 8;      // 16B-multiple when doubled
    const int h    = h0 + hl;

    __half2 acc[8];
    #pragma unroll
    for (int w = 0; w < 8; w++) acc[w] = NEG2;

    const __half* xbase = xs + hl * XS_STRIDE + w0;
    const float4* kvec  = (const float4*)(ks + (pair * IC_) * K_STRIDE);

    #pragma unroll 2
    for (int ic = 0; ic < IC_; ic++) {
        // all 9 k taps for this ic: 2x LDS.128 + 1x LDS.32
        const float4* kp = kvec + ic * (K_STRIDE / 4);
        float4 ka = kp[0];                 // taps 0..3
        float4 kb = kp[1];                 // taps 4..7
        __half2 kt[9];
        kt[0] = *(__half2*)&ka.x; kt[1] = *(__half2*)&ka.y;
        kt[2] = *(__half2*)&ka.z; kt[3] = *(__half2*)&ka.w;
        kt[4] = *(__half2*)&kb.x; kt[5] = *(__half2*)&kb.y;
        kt[6] = *(__half2*)&kb.z; kt[7] = *(__half2*)&kb.w;
        kt[8] = ((const __half2*)kp)[8];

        #pragma unroll
        for (int kh = 0; kh < 3; kh++) {
            // 10 x halves (cols w0..w0+9): LDS.128 + LDS.32, 16B aligned
            const __half* row = xbase + (ic * XROWS + kh) * XS_STRIDE;
            float4 rv = *(const float4*)row;
            __half2 V0 = *(__half2*)&rv.x;
            __half2 V1 = *(__half2*)&rv.y;
            __half2 V2 = *(__half2*)&rv.z;
            __half2 V3 = *(__half2*)&rv.w;
            __half2 V4 = *(const __half2*)(row + 8);

            __half2 X[10];
            X[0] = __low2half2(V0);  X[1] = __high2half2(V0);
            X[2] = __low2half2(V1);  X[3] = __high2half2(V1);
            X[4] = __low2half2(V2);  X[5] = __high2half2(V2);
            X[6] = __low2half2(V3);  X[7] = __high2half2(V3);
            X[8] = __low2half2(V4);  X[9] = __high2half2(V4);

            __half2 k0 = kt[kh * 3 + 0], k1 = kt[kh * 3 + 1], k2 = kt[kh * 3 + 2];
            #pragma unroll
            for (int w = 0; w < 8; w++) {
                __half2 m = __hmin2(X[w], k0);
                m = __hmax2(m, __hmin2(X[w + 1], k1));
                m = __hmax2(m, __hmin2(X[w + 2], k2));
                acc[w] = __hmax2(acc[w], m);
            }
        }
    }

    // ---- write 2 oc x 8 w outputs as f32 ----
    int oc0 = ocbase + 2 * pair;
    float4* v0 = (float4*)(out + (((size_t)n * OC_ + oc0)     * H_ + h) * W_ + w0);
    float4* v1 = (float4*)(out + (((size_t)n * OC_ + oc0 + 1) * H_ + h) * W_ + w0);
    v0[0] = make_float4(__low2float(acc[0]), __low2float(acc[1]),
                        __low2float(acc[2]), __low2float(acc[3]));
    v0[1] = make_float4(__low2float(acc[4]), __low2float(acc[5]),
                        __low2float(acc[6]), __low2float(acc[7]));
    v1[0] = make_float4(__high2float(acc[0]), __high2float(acc[1]),
                        __high2float(acc[2]), __high2float(acc[3]));
    v1[1] = make_float4(__high2float(acc[4]), __high2float(acc[5]),
                        __high2float(acc[6]), __high2float(acc[7]));
}

extern "C" void kernel_launch(void* const* d_in, const int* in_sizes, int n_in,
                              void* d_out, int out_size) {
    const float* x = (const float*)d_in[0];
    const float* k = (const float*)d_in[1];
    float* out = (float*)d_out;

    size_t smem = (size_t)IC_ * XROWS * XS_STRIDE * sizeof(__half)
                + (size_t)8 * IC_ * K_STRIDE * sizeof(__half2);   // 26624 + 12288 = 38912 B
    cudaFuncSetAttribute(semiconv2d_h2v,
                         cudaFuncAttributeMaxDynamicSharedMemorySize, (int)smem);
    dim3 grid(H_ / TILE_H, OC_ / OC_PER_BLK, N_);                  // 48 x 2 x 8 = 768
    semiconv2d_h2v<<<grid, THREADS, smem>>>(x, k, out);
}

// round 6
// speedup vs baseline: 1.2060x; 1.2060x over previous
#include <cuda_runtime.h>
#include <cuda_fp16.h>

// SemiConv2d (tropical conv): out[n,oc,h,w] = max_{ic,kh,kw} min(xpad, K)
// x: (8,32,96,96) f32, K: (32,32,3,3) f32, out f32, pad=1 with -inf.
//
// Sorted-tap early exit: taps processed in descending k order (fp16).
// Once every acc in the thread >= k[i], no remaining tap can raise the max
// (min(x,k_j) <= k_j <= k[i] <= acc) -> exact pruning, identical output.

#define N_      8
#define IC_     32
#define OC_     32
#define H_      96
#define W_      96
#define TILE_H  8
#define XROWS   10           // TILE_H + 2 halo rows
#define XS_STRIDE 104        // halves per row; col0 & cols>=97 = -inf
#define OC_PER_BLK 8
#define THREADS 768
#define NTAPS   288          // 32 ic * 9

__device__ unsigned g_taps[OC_ * NTAPS];   // per oc, sorted desc: (half_bits<<16)|row_off

// ---- prep: rank-sort taps per oc by fp16 value (desc), ties by index ----
__global__ void semiconv2d_prep(const float* __restrict__ kern) {
    __shared__ __half kv[NTAPS];
    const int oc = blockIdx.x;
    const int t  = threadIdx.x;
    __half me = __float2half_rn(kern[oc * NTAPS + t]);
    kv[t] = me;
    __syncthreads();
    int rank = 0;
    #pragma unroll 4
    for (int j = 0; j < NTAPS; j++) {
        __half kj = kv[j];
        rank += (__hgt(kj, me) || (__heq(kj, me) && j < t)) ? 1 : 0;
    }
    int ic = t / 9, r = t % 9, kh = r / 3, kw = r % 3;
    unsigned off = (unsigned)((ic * XROWS + kh) * XS_STRIDE + kw);
    g_taps[oc * NTAPS + rank] = ((unsigned)__half_as_ushort(me) << 16) | off;
}

__global__ __launch_bounds__(THREADS, 2)
void semiconv2d_sorted(const float* __restrict__ x,
                       float* __restrict__ out) {
    extern __shared__ __align__(16) char smraw[];
    __half*   xs    = (__half*)smraw;                                   // [IC][XROWS][XS_STRIDE]
    unsigned* tapss = (unsigned*)(smraw + (size_t)IC_ * XROWS * XS_STRIDE * sizeof(__half)); // [OC_PER_BLK][NTAPS]

    const int tid    = threadIdx.x;
    const int n      = blockIdx.z;
    const int ocbase = blockIdx.y * OC_PER_BLK;
    const int h0     = blockIdx.x * TILE_H;
    const __half  NEGH = __ushort_as_half((unsigned short)0xFC00);      // -inf
    const __half2 NEG2 = __half2half2(NEGH);

    // ---- fill x tile (f32 gmem -> f16 smem, -inf halo) ----
    const float* xn = x + (size_t)n * IC_ * H_ * W_;
    for (int e = tid; e < IC_ * XROWS * XS_STRIDE; e += THREADS) {
        int ic  = e / (XROWS * XS_STRIDE);
        int rem = e % (XROWS * XS_STRIDE);
        int r   = rem / XS_STRIDE;
        int c   = rem % XS_STRIDE;
        int g   = h0 - 1 + r;
        __half v = NEGH;
        if (c >= 1 && c <= W_ && g >= 0 && g < H_)
            v = __float2half_rn(xn[(ic * H_ + g) * W_ + (c - 1)]);
        xs[e] = v;
    }
    // ---- copy this block's sorted tap lists ----
    for (int e = tid; e < OC_PER_BLK * NTAPS; e += THREADS)
        tapss[e] = g_taps[ocbase * NTAPS + e];
    __syncthreads();

    // thread -> (local oc, h row, 8-wide w strip); warp is oc-uniform (96 thr/oc)
    const int ocl = tid / 96;           // 0..7
    const int s   = tid % 96;
    const int hl  = s / 12;             // 0..7
    const int w0  = (s % 12) * 8;
    const int h   = h0 + hl;

    // acc[j] = (out[w0+2j], out[w0+2j+1])
    __half2 acc0 = NEG2, acc1 = NEG2, acc2 = NEG2, acc3 = NEG2;

    const __half*   xb = xs + hl * XS_STRIDE + w0;   // add row_off from tap
    const unsigned* tp = tapss + ocl * NTAPS;

    #pragma unroll 1
    for (int i = 0; i < NTAPS; i++) {
        unsigned rec = tp[i];
        __half kf = __ushort_as_half((unsigned short)(rec >> 16));
        // exact early exit: all 8 accs >= kf?
        __half2 m01 = __hmin2(acc0, acc1);
        __half2 m23 = __hmin2(acc2, acc3);
        __half2 m   = __hmin2(m01, m23);
        __half  mn  = __hmin(__low2half(m), __high2half(m));
        if (!__hlt(mn, kf)) break;

        unsigned off = rec & 0xffffu;
        const __half* row = xb + off;               // x[tile_row][w0+kw]
        __half2 k2 = __half2half2(kf);
        __half2 X0, X1, X2, X3;
        if (off & 1u) {
            // kw odd: build shifted pairs from aligned loads
            const __half2* ra = (const __half2*)(row - 1);
            __half2 V0 = ra[0], V1 = ra[1], V2 = ra[2], V3 = ra[3], V4 = ra[4];
            X0 = __halves2half2(__high2half(V0), __low2half(V1));
            X1 = __halves2half2(__high2half(V1), __low2half(V2));
            X2 = __halves2half2(__high2half(V2), __low2half(V3));
            X3 = __halves2half2(__high2half(V3), __low2half(V4));
        } else {
            const __half2* ra = (const __half2*)row;
            X0 = ra[0]; X1 = ra[1]; X2 = ra[2]; X3 = ra[3];
        }
        acc0 = __hmax2(acc0, __hmin2(X0, k2));
        acc1 = __hmax2(acc1, __hmin2(X1, k2));
        acc2 = __hmax2(acc2, __hmin2(X2, k2));
        acc3 = __hmax2(acc3, __hmin2(X3, k2));
    }

    // ---- write 8 w outputs as f32 ----
    int oc = ocbase + ocl;
    float4* o = (float4*)(out + (((size_t)n * OC_ + oc) * H_ + h) * W_ + w0);
    float2 f0 = __half22float2(acc0);
    float2 f1 = __half22float2(acc1);
    float2 f2 = __half22float2(acc2);
    float2 f3 = __half22float2(acc3);
    o[0] = make_float4(f0.x, f0.y, f1.x, f1.y);
    o[1] = make_float4(f2.x, f2.y, f3.x, f3.y);
}

extern "C" void kernel_launch(void* const* d_in, const int* in_sizes, int n_in,
                              void* d_out, int out_size) {
    const float* x = (const float*)d_in[0];
    const float* k = (const float*)d_in[1];
    float* out = (float*)d_out;

    semiconv2d_prep<<<OC_, NTAPS>>>(k);

    size_t smem = (size_t)IC_ * XROWS * XS_STRIDE * sizeof(__half)
                + (size_t)OC_PER_BLK * NTAPS * sizeof(unsigned);   // 66560 + 9216 = 75776 B
    cudaFuncSetAttribute(semiconv2d_sorted,
                         cudaFuncAttributeMaxDynamicSharedMemorySize, (int)smem);
    dim3 grid(H_ / TILE_H, OC_ / OC_PER_BLK, N_);                  // 12 x 4 x 8 = 384
    semiconv2d_sorted<<<grid, THREADS, smem>>>(x, out);
}